// round 6
// baseline (speedup 1.0000x reference)
#include <cuda_runtime.h>
#include <math_constants.h>

// MAM dense: C[n,j] = max_k(x[n,k]*w[j,k]) + min_k(x[n,k]*w[j,k]) + bias[j]
// x: [2048, 512] f32, w: [256, 512] f32, bias: [256] f32, out: [2048, 256] f32
//
// R5: kill the LDS-wavefront bottleneck (R3's real binder: L1=77% vs alu=36%).
//  - x lives in REGISTERS (8 float4 per 32-k chunk, per-thread row). Zero x smem.
//  - w tile [8j x 32k] j-major in smem; inner LDS.128 is warp-UNIFORM
//    (broadcast, ~1 wavefront) and feeds 4 FMUL + 8 FMNMX.
//  - Tile 64n x 8j, 128 threads (4 warps -> all SMSPs), 2 threads/row x 4j.
//  - Grid 1024 CTAs -> 7v6 per-SM balance (+3.5% over the 56.7K-cycle alu floor).
//  - Double-buffered w smem, gmem prefetch, tree min/max for ILP.

constexpr int IN_F  = 512;
constexpr int OUT_F = 256;
constexpr int NROWS = 2048;

constexpr int TN = 64;                     // n per CTA
constexpr int TJ = 8;                      // j per CTA
constexpr int KB = 32;                     // k chunk
constexpr int NCH = IN_F / KB;             // 16
constexpr int TILES_J = OUT_F / TJ;        // 32
constexpr int NTILES  = (NROWS / TN) * TILES_J;  // 1024
constexpr int THREADS = 128;

__global__ __launch_bounds__(THREADS)
void mam_kernel(const float* __restrict__ x,
                const float* __restrict__ w,
                const float* __restrict__ bias,
                float* __restrict__ out)
{
    __shared__ __align__(16) float ws[2][TJ][KB];   // 2 KB double buffer

    const int tid = threadIdx.x;
    const int r   = tid >> 1;          // row in tile: 0..63
    const int jh  = (tid & 1) * 4;     // j half: 0 or 4
    const int j0  = (blockIdx.x & (TILES_J - 1)) * TJ;
    const int n0  = (blockIdx.x / TILES_J) * TN;

    const float* xrow = x + (n0 + r) * IN_F;

    // w loader: first 64 threads, one float4 each per chunk.
    const bool wload = tid < (TJ * KB / 4);          // 64 threads
    const int  wjr   = tid >> 3;                     // 0..7
    const int  wkq   = (tid & 7) * 4;                // 0,4,...,28
    const float* wptr = w + (j0 + wjr) * IN_F + wkq;

    float mx[4], mn[4];
#pragma unroll
    for (int i = 0; i < 4; i++) { mx[i] = -CUDART_INF_F; mn[i] = CUDART_INF_F; }

    float4 xa[8], xb[8];
    float4 wva, wvb;

    // Prologue: chunk 0 -> xa / ws[0]
    if (wload) wva = *reinterpret_cast<const float4*>(wptr);
#pragma unroll
    for (int i = 0; i < 8; i++)
        xa[i] = *reinterpret_cast<const float4*>(xrow + i * 4);
    if (wload)
        *reinterpret_cast<float4*>(&ws[0][wjr][wkq]) = wva;
    __syncthreads();

#define COMPUTE(BUF, XV)                                                      \
    {                                                                         \
        _Pragma("unroll")                                                     \
        for (int j = 0; j < 4; j++) {                                         \
            _Pragma("unroll")                                                 \
            for (int kq = 0; kq < 8; kq++) {                                  \
                const float4 b = *reinterpret_cast<const float4*>(            \
                    &ws[BUF][jh + j][kq * 4]);                                \
                const float4 a = XV[kq];                                      \
                const float p0 = a.x * b.x, p1 = a.y * b.y;                   \
                const float p2 = a.z * b.z, p3 = a.w * b.w;                   \
                const float hx = fmaxf(fmaxf(p0, p1), fmaxf(p2, p3));         \
                const float hn = fminf(fminf(p0, p1), fminf(p2, p3));         \
                mx[j] = fmaxf(mx[j], hx);                                     \
                mn[j] = fminf(mn[j], hn);                                     \
            }                                                                 \
        }                                                                     \
    }

    for (int c = 0; c < NCH; c += 2) {
        // --- chunk c (buffer 0, regs xa); prefetch chunk c+1 ---
        const int k1 = (c + 1) * KB;
        if (wload) wvb = *reinterpret_cast<const float4*>(wptr + k1);
#pragma unroll
        for (int i = 0; i < 8; i++)
            xb[i] = *reinterpret_cast<const float4*>(xrow + k1 + i * 4);

        COMPUTE(0, xa)

        if (wload)
            *reinterpret_cast<float4*>(&ws[1][wjr][wkq]) = wvb;
        __syncthreads();

        // --- chunk c+1 (buffer 1, regs xb); prefetch chunk c+2 ---
        const bool more = (c + 2) < NCH;
        const int k2 = (c + 2) * KB;
        if (more) {
            if (wload) wva = *reinterpret_cast<const float4*>(wptr + k2);
#pragma unroll
            for (int i = 0; i < 8; i++)
                xa[i] = *reinterpret_cast<const float4*>(xrow + k2 + i * 4);
        }

        COMPUTE(1, xb)

        if (more) {
            if (wload)
                *reinterpret_cast<float4*>(&ws[0][wjr][wkq]) = wva;
            __syncthreads();
        }
    }
#undef COMPUTE

    // Epilogue: C = max + min + bias (one STG.128 per thread)
    const float4 bz = *reinterpret_cast<const float4*>(&bias[j0 + jh]);
    float4 res;
    res.x = mx[0] + mn[0] + bz.x;
    res.y = mx[1] + mn[1] + bz.y;
    res.z = mx[2] + mn[2] + bz.z;
    res.w = mx[3] + mn[3] + bz.w;
    *reinterpret_cast<float4*>(&out[(n0 + r) * OUT_F + j0 + jh]) = res;
}

extern "C" void kernel_launch(void* const* d_in, const int* in_sizes, int n_in,
                              void* d_out, int out_size)
{
    const float* x    = (const float*)d_in[0];   // [2048, 512]
    const float* w    = (const float*)d_in[1];   // [256, 512]
    const float* bias = (const float*)d_in[2];   // [256]
    float* out        = (float*)d_out;           // [2048, 256]

    mam_kernel<<<NTILES, THREADS>>>(x, w, bias, out);
}

// round 8
// speedup vs baseline: 1.7075x; 1.7075x over previous
#include <cuda_runtime.h>
#include <math_constants.h>

// MAM dense: C[n,j] = max_k(x[n,k]*w[j,k]) + min_k(x[n,k]*w[j,k]) + bias[j]
// x: [2048, 512] f32, w: [256, 512] f32, bias: [256] f32, out: [2048, 256] f32
//
// R7: l1tex-wavefront-lean version of R3.
//  - 1024 CTAs (tile 32n x 16j) -> 7v6 CTA/SM balance (+1.2% over alu floor).
//  - 128 threads, thread tile 2n x 2j: inner k = 2x LDS.64 (2 wavefronts/warp)
//    feeding 4 FMUL + 8 FMNMX -> alu-pipe-bound, not l1tex-bound.
//  - Coalesced LDG (4 rows/warp -> 4 lines per LDG.128), k-major STS with
//    strides 34/18 (max 2-way bank conflict).
//  - __launch_bounds__(128,7): regs<=72 -> 7 CTAs/SM, 7 warps/SMSP.

constexpr int IN_F  = 512;
constexpr int OUT_F = 256;
constexpr int NROWS = 2048;

constexpr int TN = 32;                     // n per CTA
constexpr int TJ = 16;                     // j per CTA
constexpr int KB = 32;                     // k chunk
constexpr int NCH = IN_F / KB;             // 16
constexpr int TILES_J = OUT_F / TJ;        // 16
constexpr int NTILES  = (NROWS / TN) * TILES_J;  // 1024
constexpr int THREADS = 128;

constexpr int XLD = 34;  // xs[k][n] row stride (even: LDS.64-aligned; 2-way STS max)
constexpr int WLD = 18;  // ws[k][j] row stride

__global__ __launch_bounds__(THREADS, 7)
void mam_kernel(const float* __restrict__ x,
                const float* __restrict__ w,
                const float* __restrict__ bias,
                float* __restrict__ out)
{
    __shared__ __align__(16) float xs[KB][XLD];   // k-major x tile
    __shared__ __align__(16) float ws[KB][WLD];   // k-major w tile

    const int tid = threadIdx.x;
    const int tn4 = tid >> 3;          // 0..15 -> n pair index
    const int tj3 = tid & 7;           // 0..7  -> j pair index
    const int j0  = (blockIdx.x & (TILES_J - 1)) * TJ;
    const int n0  = (blockIdx.x / TILES_J) * TN;

    // Loader mapping (coalesced: 4 consecutive rows per warp).
    const int lr  = tid >> 3;          // 0..15 (row sub-index)
    const int lkq = (tid & 7) * 4;     // k quad: 0,4,...,28

    const float* xb = &x[(n0 + lr) * IN_F + lkq];        // rows lr and lr+16
    const float* wb = &w[(j0 + lr) * IN_F + lkq];        // row lr (lr<16 always)

    float mx[2][2], mn[2][2];
#pragma unroll
    for (int i = 0; i < 2; i++)
#pragma unroll
        for (int jj = 0; jj < 2; jj++) {
            mx[i][jj] = -CUDART_INF_F;
            mn[i][jj] =  CUDART_INF_F;
        }

    // Prefetch chunk 0.
    float4 xv0 = *reinterpret_cast<const float4*>(xb);
    float4 xv1 = *reinterpret_cast<const float4*>(xb + 16 * IN_F);
    float4 wv  = *reinterpret_cast<const float4*>(wb);

    const float* agp = &xs[0][2 * tn4];
    const float* bgp = &ws[0][2 * tj3];

    for (int c = 0; c < NCH; c++) {
        // STS prefetched chunk (k-major).
        xs[lkq + 0][lr]      = xv0.x; xs[lkq + 1][lr]      = xv0.y;
        xs[lkq + 2][lr]      = xv0.z; xs[lkq + 3][lr]      = xv0.w;
        xs[lkq + 0][lr + 16] = xv1.x; xs[lkq + 1][lr + 16] = xv1.y;
        xs[lkq + 2][lr + 16] = xv1.z; xs[lkq + 3][lr + 16] = xv1.w;
        ws[lkq + 0][lr] = wv.x; ws[lkq + 1][lr] = wv.y;
        ws[lkq + 2][lr] = wv.z; ws[lkq + 3][lr] = wv.w;
        __syncthreads();

        // Prefetch next chunk while computing this one.
        if (c + 1 < NCH) {
            const int kn = (c + 1) * KB;
            xv0 = *reinterpret_cast<const float4*>(xb + kn);
            xv1 = *reinterpret_cast<const float4*>(xb + 16 * IN_F + kn);
            wv  = *reinterpret_cast<const float4*>(wb + kn);
        }

#pragma unroll
        for (int k = 0; k < KB; k++) {
            const float2 a = *reinterpret_cast<const float2*>(agp + k * XLD);
            const float2 b = *reinterpret_cast<const float2*>(bgp + k * WLD);
            float p;
            p = a.x * b.x; mx[0][0] = fmaxf(mx[0][0], p); mn[0][0] = fminf(mn[0][0], p);
            p = a.x * b.y; mx[0][1] = fmaxf(mx[0][1], p); mn[0][1] = fminf(mn[0][1], p);
            p = a.y * b.x; mx[1][0] = fmaxf(mx[1][0], p); mn[1][0] = fminf(mn[1][0], p);
            p = a.y * b.y; mx[1][1] = fmaxf(mx[1][1], p); mn[1][1] = fminf(mn[1][1], p);
        }
        __syncthreads();
    }

    // Epilogue: C = max + min + bias (two STG.64).
    const int j = j0 + 2 * tj3;
    const int n = n0 + 2 * tn4;
    const float b0 = bias[j];
    const float b1 = bias[j + 1];
#pragma unroll
    for (int i = 0; i < 2; i++) {
        float2 r;
        r.x = mx[i][0] + mn[i][0] + b0;
        r.y = mx[i][1] + mn[i][1] + b1;
        *reinterpret_cast<float2*>(&out[(n + i) * OUT_F + j]) = r;
    }
}

extern "C" void kernel_launch(void* const* d_in, const int* in_sizes, int n_in,
                              void* d_out, int out_size)
{
    const float* x    = (const float*)d_in[0];   // [2048, 512]
    const float* w    = (const float*)d_in[1];   // [256, 512]
    const float* bias = (const float*)d_in[2];   // [256]
    float* out        = (float*)d_out;           // [2048, 256]

    mam_kernel<<<NTILES, THREADS>>>(x, w, bias, out);
}

// round 10
// speedup vs baseline: 1.7104x; 1.0017x over previous
#include <cuda_runtime.h>
#include <math_constants.h>

// MAM dense: C[n,j] = max_k(x[n,k]*w[j,k]) + min_k(x[n,k]*w[j,k]) + bias[j]
// x: [2048, 512] f32, w: [256, 512] f32, bias: [256] f32, out: [2048, 256] f32
//
// R9: halve inner-loop LDS traffic via k-paired smem layout.
//  - sm_103a FP32 rt=1/SMSP (verified from R7 pipe% vs instr counts) ->
//    alu floor ~16us; binder is l1tex (78%). Cut LDS instrs per math op.
//  - smem packs k-pairs: xs2[k2][n][2] / ws2[k2][j][2]. One LDS.128 = 2k x 2n
//    (a) or 2k x 2j (b): 2 LDS.128 per TWO k -> 8 FMUL + 16 FMNMX.
//  - Staging: 2x STS.64 per LDG float4, stride 68/36 floats (2-way max).
//  - Grid/tile identical to R7 (1024 CTAs, 32n x 16j, 128 thr, 7v6 balance).

constexpr int IN_F  = 512;
constexpr int OUT_F = 256;
constexpr int NROWS = 2048;

constexpr int TN = 32;
constexpr int TJ = 16;
constexpr int KB = 32;
constexpr int NCH = IN_F / KB;             // 16
constexpr int TILES_J = OUT_F / TJ;        // 16
constexpr int NTILES  = (NROWS / TN) * TILES_J;  // 1024
constexpr int THREADS = 128;

constexpr int XLD2 = 68;   // floats per k2-row of xs2 (17*16B: aligned, 2-way STS max)
constexpr int WLD2 = 36;   // floats per k2-row of ws2 (9*16B)

__global__ __launch_bounds__(THREADS, 7)
void mam_kernel(const float* __restrict__ x,
                const float* __restrict__ w,
                const float* __restrict__ bias,
                float* __restrict__ out)
{
    // k-pair-packed tiles: xs2[k2][n][2] (k parity innermost), ws2[k2][j][2].
    __shared__ __align__(16) float xs2[(KB / 2) * XLD2];
    __shared__ __align__(16) float ws2[(KB / 2) * WLD2];

    const int tid = threadIdx.x;
    const int tn4 = tid >> 3;          // 0..15 -> n pair
    const int tj3 = tid & 7;           // 0..7  -> j pair
    const int j0  = (blockIdx.x & (TILES_J - 1)) * TJ;
    const int n0  = (blockIdx.x / TILES_J) * TN;

    // Loader mapping (coalesced: 4 consecutive rows per warp quarter).
    const int lr  = tid >> 3;          // 0..15
    const int lkq = (tid & 7) * 4;     // 0,4,...,28
    const int lk2 = lkq >> 1;          // k2 base: 0,2,...,14

    const float* xb = &x[(n0 + lr) * IN_F + lkq];   // rows lr, lr+16
    const float* wb = &w[(j0 + lr) * IN_F + lkq];   // row lr

    float mx[2][2], mn[2][2];
#pragma unroll
    for (int i = 0; i < 2; i++)
#pragma unroll
        for (int jj = 0; jj < 2; jj++) {
            mx[i][jj] = -CUDART_INF_F;
            mn[i][jj] =  CUDART_INF_F;
        }

    // Prefetch chunk 0.
    float4 xv0 = *reinterpret_cast<const float4*>(xb);
    float4 xv1 = *reinterpret_cast<const float4*>(xb + 16 * IN_F);
    float4 wv  = *reinterpret_cast<const float4*>(wb);

    const float* agp = xs2 + 4 * tn4;   // LDS.128 base (byte 16*tn4)
    const float* bgp = ws2 + 4 * tj3;   // LDS.128 base (byte 16*tj3)

    for (int c = 0; c < NCH; c++) {
        // STS prefetched chunk: k-pair packing, 2x STS.64 per float4.
        {
            float* xa = xs2 + lk2 * XLD2 + 2 * lr;
            *reinterpret_cast<float2*>(xa)        = make_float2(xv0.x, xv0.y);
            *reinterpret_cast<float2*>(xa + XLD2) = make_float2(xv0.z, xv0.w);
            float* xc = xs2 + lk2 * XLD2 + 2 * (lr + 16);
            *reinterpret_cast<float2*>(xc)        = make_float2(xv1.x, xv1.y);
            *reinterpret_cast<float2*>(xc + XLD2) = make_float2(xv1.z, xv1.w);
            float* wa = ws2 + lk2 * WLD2 + 2 * lr;
            *reinterpret_cast<float2*>(wa)        = make_float2(wv.x, wv.y);
            *reinterpret_cast<float2*>(wa + WLD2) = make_float2(wv.z, wv.w);
        }
        __syncthreads();

        // Prefetch next chunk while computing this one.
        if (c + 1 < NCH) {
            const int kn = (c + 1) * KB;
            xv0 = *reinterpret_cast<const float4*>(xb + kn);
            xv1 = *reinterpret_cast<const float4*>(xb + 16 * IN_F + kn);
            wv  = *reinterpret_cast<const float4*>(wb + kn);
        }

#pragma unroll
        for (int k2 = 0; k2 < KB / 2; k2++) {
            // a = {x[k0,n0], x[k1,n0], x[k0,n1], x[k1,n1]}
            // b = {w[k0,j0], w[k1,j0], w[k0,j1], w[k1,j1]}
            const float4 a = *reinterpret_cast<const float4*>(agp + k2 * XLD2);
            const float4 b = *reinterpret_cast<const float4*>(bgp + k2 * WLD2);

            const float p000 = a.x * b.x;  // (n0,j0,k0)
            const float p001 = a.y * b.y;  // (n0,j0,k1)
            const float p010 = a.x * b.z;  // (n0,j1,k0)
            const float p011 = a.y * b.w;  // (n0,j1,k1)
            const float p100 = a.z * b.x;  // (n1,j0,k0)
            const float p101 = a.w * b.y;  // (n1,j0,k1)
            const float p110 = a.z * b.z;  // (n1,j1,k0)
            const float p111 = a.w * b.w;  // (n1,j1,k1)

            mx[0][0] = fmaxf(mx[0][0], fmaxf(p000, p001));
            mn[0][0] = fminf(mn[0][0], fminf(p000, p001));
            mx[0][1] = fmaxf(mx[0][1], fmaxf(p010, p011));
            mn[0][1] = fminf(mn[0][1], fminf(p010, p011));
            mx[1][0] = fmaxf(mx[1][0], fmaxf(p100, p101));
            mn[1][0] = fminf(mn[1][0], fminf(p100, p101));
            mx[1][1] = fmaxf(mx[1][1], fmaxf(p110, p111));
            mn[1][1] = fminf(mn[1][1], fminf(p110, p111));
        }
        __syncthreads();
    }

    // Epilogue: C = max + min + bias (two STG.64).
    const int j = j0 + 2 * tj3;
    const int n = n0 + 2 * tn4;
    const float b0 = bias[j];
    const float b1 = bias[j + 1];
#pragma unroll
    for (int i = 0; i < 2; i++) {
        float2 r;
        r.x = mx[i][0] + mn[i][0] + b0;
        r.y = mx[i][1] + mn[i][1] + b1;
        *reinterpret_cast<float2*>(&out[(n + i) * OUT_F + j]) = r;
    }
}

extern "C" void kernel_launch(void* const* d_in, const int* in_sizes, int n_in,
                              void* d_out, int out_size)
{
    const float* x    = (const float*)d_in[0];   // [2048, 512]
    const float* w    = (const float*)d_in[1];   // [256, 512]
    const float* bias = (const float*)d_in[2];   // [256]
    float* out        = (float*)d_out;           // [2048, 256]

    mam_kernel<<<NTILES, THREADS>>>(x, w, bias, out);
}